// round 11
// baseline (speedup 1.0000x reference)
#include <cuda_runtime.h>
#include <cuda_fp16.h>

#define SS 512
#define CC 64
#define VV 4
#define NFACES 400000
#define NP (SS*SS)             // 262144 pixels per view
#define VW ((NFACES+31)/32)    // 12500 words per view bitmask
#define NMAX 200000
#define NB 4096                // sort buckets: 64x64 tiles of 8x8 pixels

// Scratch (static device allocations; no runtime mallocs allowed)
__device__ __align__(128) __half g_featT[(size_t)VV * NP * CC]; // 128 MiB, channel-last fp16
__device__ unsigned g_vis[VV * VW];      // per-view face visibility bitmask
__device__ float    g_P[VV * 12];        // fused camera: rows of K@R (3x3) + K@t, [r*4+c]
__device__ int      g_key[NMAX];         // per-vertex bucket key
__device__ int      g_perm[NMAX];        // sorted vertex order
__device__ unsigned g_hist[NB];          // bucket histogram
__device__ unsigned g_off[NB];           // bucket exclusive offsets (consumed by scatter)

// ---------------------------------------------------------------------------
// 1. clear visibility bitmask + histogram
__global__ void clear_kernel() {
    int i = blockIdx.x * blockDim.x + threadIdx.x;
    if (i < VV * VW) g_vis[i] = 0u;
    if (i < NB) g_hist[i] = 0u;
}

// 2. scatter pix_to_face into visibility bitmask
__global__ void scatter_vis_kernel(const int* __restrict__ p2f) {
    int i = blockIdx.x * blockDim.x + threadIdx.x;
    if (i >= VV * NP) return;
    int f = __ldcs(&p2f[i]);
    if (f >= 0) {
        int v = i >> 18; // i / NP
        atomicOr(&g_vis[v * VW + (f >> 5)], 1u << (f & 31));
    }
}

// 3. fuse cameras: P = K@R, q = K@t
__global__ void cam_kernel(const float* __restrict__ Rm, const float* __restrict__ tm,
                           const float* __restrict__ Km) {
    int v = threadIdx.x;
    if (v >= VV) return;
    const float* R = Rm + v * 9;
    const float* t = tm + v * 3;
    const float* K = Km + v * 9;
    #pragma unroll
    for (int r = 0; r < 3; r++) {
        #pragma unroll
        for (int c = 0; c < 3; c++)
            g_P[v * 12 + r * 4 + c] = K[r*3+0]*R[0*3+c] + K[r*3+1]*R[1*3+c] + K[r*3+2]*R[2*3+c];
        g_P[v * 12 + r * 4 + 3] = K[r*3+0]*t[0] + K[r*3+1]*t[1] + K[r*3+2]*t[2];
    }
}

// shared projection: raw pixel-space xy for (vertex, view)
__device__ __forceinline__ void proj_xy(float px, float py, float pz, int v,
                                        float* x, float* y) {
    const float* P = g_P + v * 12;
    float u  = P[0]*px + P[1]*py + P[2] *pz + P[3];
    float w_ = P[4]*px + P[5]*py + P[6] *pz + P[7];
    float zz = P[8]*px + P[9]*py + P[10]*pz + P[11];
    float rz = __frcp_rn(zz);
    *x = u * rz; *y = w_ * rz;
}

// 4a. sort keys: bucket by view-0 projected pixel (8x8 tiles) + histogram
__global__ __launch_bounds__(256) void key_kernel(const float* __restrict__ verts, int n) {
    int i = blockIdx.x * blockDim.x + threadIdx.x;
    if (i >= n) return;
    float x, y;
    proj_xy(verts[3*i], verts[3*i+1], verts[3*i+2], 0, &x, &y);
    int xi = (int)fminf(fmaxf(x, 0.0f), (float)(SS-1));
    int yi = (int)fminf(fmaxf(y, 0.0f), (float)(SS-1));
    int key = (yi >> 3) * 64 + (xi >> 3);
    g_key[i] = key;
    atomicAdd(&g_hist[key], 1u);
}

// 4b. exclusive prefix scan over NB=4096 buckets (one block, 1024 threads, 4/thread)
__global__ __launch_bounds__(1024) void prefix_kernel() {
    __shared__ unsigned s[1024];
    int t = threadIdx.x;
    unsigned v0 = g_hist[4*t], v1 = g_hist[4*t+1], v2 = g_hist[4*t+2], v3 = g_hist[4*t+3];
    unsigned sum = v0 + v1 + v2 + v3;
    s[t] = sum;
    __syncthreads();
    for (int d = 1; d < 1024; d <<= 1) {
        unsigned x = (t >= d) ? s[t - d] : 0u;
        __syncthreads();
        s[t] += x;
        __syncthreads();
    }
    unsigned excl = s[t] - sum;
    g_off[4*t]   = excl;
    g_off[4*t+1] = excl + v0;
    g_off[4*t+2] = excl + v0 + v1;
    g_off[4*t+3] = excl + v0 + v1 + v2;
}

// 4c. scatter vertex ids into sorted order
__global__ __launch_bounds__(256) void scatter_perm_kernel(int n) {
    int i = blockIdx.x * blockDim.x + threadIdx.x;
    if (i >= n) return;
    unsigned pos = atomicAdd(&g_off[g_key[i]], 1u);
    g_perm[pos] = i;
}

// 5. transpose feature [V,C,S,S] fp32 -> [V,S,S,C] fp16 (proven R7 monolith)
__global__ __launch_bounds__(256) void transpose_feat_kernel(const float* __restrict__ feat) {
    __shared__ float tile[CC][33];
    int v  = blockIdx.y;
    int p0 = blockIdx.x * 32;
    const float* in = feat + (size_t)v * CC * NP + p0;
    int tx = threadIdx.x & 31, tw = threadIdx.x >> 5;
    #pragma unroll
    for (int j = 0; j < 8; j++) {
        int r = tw * 8 + j;
        tile[r][tx] = __ldcs(&in[(size_t)r * NP + tx]);
    }
    __syncthreads();
    __half2* out = ((__half2*)g_featT) + ((size_t)v * NP + p0) * 32;
    int cp = tx;
    int pb = tw;
    #pragma unroll
    for (int k = 0; k < 4; k++) {
        int p = pb + k * 8;
        __half2 h = __floats2half2_rn(tile[2*cp][p], tile[2*cp+1][p]);
        out[(size_t)p * 32 + cp] = h;
    }
}

// accumulate 8 fp16 channels (one uint4) with weight w into acc[8]
__device__ __forceinline__ void accum8(float* acc, uint4 q, float w) {
    __half2 h0 = *(__half2*)&q.x, h1 = *(__half2*)&q.y;
    __half2 h2 = *(__half2*)&q.z, h3 = *(__half2*)&q.w;
    float2 f0 = __half22float2(h0), f1 = __half22float2(h1);
    float2 f2 = __half22float2(h2), f3 = __half22float2(h3);
    acc[0] = fmaf(w, f0.x, acc[0]); acc[1] = fmaf(w, f0.y, acc[1]);
    acc[2] = fmaf(w, f1.x, acc[2]); acc[3] = fmaf(w, f1.y, acc[3]);
    acc[4] = fmaf(w, f2.x, acc[4]); acc[5] = fmaf(w, f2.y, acc[5]);
    acc[6] = fmaf(w, f3.x, acc[6]); acc[7] = fmaf(w, f3.y, acc[7]);
}

// 6. fused meta + gather over SORTED vertex order: 32 vertices per 256-thread block.
//    Sorted order clusters corner reads onto shared 128B featT lines (L1/L2 reuse).
__global__ __launch_bounds__(256) void gather_kernel(
    float* __restrict__ out,
    const float* __restrict__ verts, const int* __restrict__ faces, int n)
{
    __shared__ int    s_idx[32];
    __shared__ int4   s_off[32][VV];
    __shared__ float4 s_w[32][VV];

    int vb = blockIdx.x * 32;
    int t  = threadIdx.x;

    if (t < 32) {
        int i = vb + t;
        s_idx[t] = (i < n) ? g_perm[i] : -1;
    }
    __syncthreads();

    if (t < 128) {
        int j = t >> 2, v = t & 3;
        int ip = s_idx[j];
        if (ip >= 0) {
            float px = verts[3*ip], py = verts[3*ip+1], pz = verts[3*ip+2];
            int f = faces[ip];
            int msum = 0, mv = 0;
            #pragma unroll
            for (int vv = 0; vv < VV; vv++) {
                int b = (g_vis[vv * VW + (f >> 5)] >> (f & 31)) & 1;
                msum += b;
                if (vv == v) mv = b;
            }
            float inv = 1.0f / (float)(msum ? msum : VV);
            float bw  = (msum ? (float)mv : 1.0f) * inv;

            float x, y;
            proj_xy(px, py, pz, v, &x, &y);
            float x0f = floorf(x), y0f = floorf(y);
            float x1f = x0f + 1.0f, y1f = y0f + 1.0f;
            float wx1 = x - x0f, wx0 = 1.0f - wx1;
            float wy1 = y - y0f, wy0 = 1.0f - wy1;

            bool vx0 = (x0f >= 0.0f) && (x0f <= (float)(SS-1));
            bool vx1 = (x1f >= 0.0f) && (x1f <= (float)(SS-1));
            bool vy0 = (y0f >= 0.0f) && (y0f <= (float)(SS-1));
            bool vy1 = (y1f >= 0.0f) && (y1f <= (float)(SS-1));

            int xc0 = (int)fminf(fmaxf(x0f, 0.0f), (float)(SS-1));
            int xc1 = (int)fminf(fmaxf(x1f, 0.0f), (float)(SS-1));
            int yc0 = (int)fminf(fmaxf(y0f, 0.0f), (float)(SS-1));
            int yc1 = (int)fminf(fmaxf(y1f, 0.0f), (float)(SS-1));

            int baseV = v * NP;
            s_off[j][v] = make_int4((baseV + yc0 * SS + xc0) * 8,
                                    (baseV + yc0 * SS + xc1) * 8,
                                    (baseV + yc1 * SS + xc0) * 8,
                                    (baseV + yc1 * SS + xc1) * 8);
            float4 wq;
            wq.x = bw * wx0 * wy0 * (float)(vx0 && vy0);
            wq.y = bw * wx1 * wy0 * (float)(vx1 && vy0);
            wq.z = bw * wx0 * wy1 * (float)(vx0 && vy1);
            wq.w = bw * wx1 * wy1 * (float)(vx1 && vy1);
            s_w[j][v] = wq;
        }
    }
    __syncthreads();

    int j = t >> 3;
    int ip = s_idx[j];
    int ck = t & 7;           // channel chunk (8 channels)
    if (ip < 0) return;

    const uint4* B = (const uint4*)g_featT;
    float acc[8] = {0.f,0.f,0.f,0.f,0.f,0.f,0.f,0.f};
    #pragma unroll
    for (int v = 0; v < VV; v++) {
        float4 w = s_w[j][v];
        if (w.x + w.y + w.z + w.w != 0.0f) {
            int4 o = s_off[j][v];
            uint4 fa = B[o.x + ck];
            uint4 fb = B[o.y + ck];
            uint4 fc = B[o.z + ck];
            uint4 fd = B[o.w + ck];
            accum8(acc, fa, w.x);
            accum8(acc, fb, w.y);
            accum8(acc, fc, w.z);
            accum8(acc, fd, w.w);
        }
    }
    float4* O = (float4*)(out + (size_t)ip * CC + ck * 8);
    __stcs(O,     make_float4(acc[0], acc[1], acc[2], acc[3]));
    __stcs(O + 1, make_float4(acc[4], acc[5], acc[6], acc[7]));
}

// ---------------------------------------------------------------------------
// Side stream + events: created once (first call is the uncaptured correctness
// run); reused every call so captured work is identical.
static cudaStream_t g_s1 = nullptr;
static cudaEvent_t  g_eFork = nullptr, g_eSide = nullptr;

extern "C" void kernel_launch(void* const* d_in, const int* in_sizes, int n_in,
                              void* d_out, int out_size) {
    const float* verts = nullptr;
    const int*   faces = nullptr;
    const float* Rm = nullptr, *tm = nullptr, *Km = nullptr, *feat = nullptr;
    const int*   p2f = nullptr;
    int n36 = 0;
    for (int i = 0; i < n_in; i++) {
        int s = in_sizes[i];
        if      (s == 600000)   verts = (const float*)d_in[i];
        else if (s == 200000)   faces = (const int*)d_in[i];
        else if (s == 36)       { if (n36++ == 0) Rm = (const float*)d_in[i]; else Km = (const float*)d_in[i]; }
        else if (s == 12)       tm = (const float*)d_in[i];
        else if (s == 67108864) feat = (const float*)d_in[i];
        else if (s == 1048576)  p2f = (const int*)d_in[i];
    }
    int n = 200000;

    if (g_s1 == nullptr) {
        cudaStreamCreateWithFlags(&g_s1, cudaStreamNonBlocking);
        cudaEventCreateWithFlags(&g_eFork, cudaEventDisableTiming);
        cudaEventCreateWithFlags(&g_eSide, cudaEventDisableTiming);
    }

    // fork: side stream runs vis chain + camera + vertex sort (hidden under transpose)
    cudaEventRecord(g_eFork, 0);
    cudaStreamWaitEvent(g_s1, g_eFork, 0);
    clear_kernel<<<(VV * VW + 255) / 256, 256, 0, g_s1>>>();
    scatter_vis_kernel<<<(VV * NP + 255) / 256, 256, 0, g_s1>>>(p2f);
    cam_kernel<<<1, 32, 0, g_s1>>>(Rm, tm, Km);
    key_kernel<<<(n + 255) / 256, 256, 0, g_s1>>>(verts, n);
    prefix_kernel<<<1, 1024, 0, g_s1>>>();
    scatter_perm_kernel<<<(n + 255) / 256, 256, 0, g_s1>>>(n);
    cudaEventRecord(g_eSide, g_s1);

    // main stream: full transpose (the DRAM-bound long pole)
    transpose_feat_kernel<<<dim3(NP / 32, VV), 256>>>(feat);

    // join: gather over sorted vertex order
    cudaStreamWaitEvent(0, g_eSide, 0);
    gather_kernel<<<(n + 31) / 32, 256>>>((float*)d_out, verts, faces, n);
}